// round 2
// baseline (speedup 1.0000x reference)
#include <cuda_runtime.h>

#define DOUT 128
#define EDIM 16
#define MAX_NODES 100000

// Scratch for xw = x @ W  (51.2 MB, L2-resident during edge phase)
__device__ float g_xw[(size_t)MAX_NODES * DOUT];

// out[n][c] = b[c]  (bias pre-folded; scatter accumulates on top)
__global__ void init_out_kernel(const float* __restrict__ b,
                                float4* __restrict__ out, int n4) {
    int i = blockIdx.x * blockDim.x + threadIdx.x;
    if (i >= n4) return;
    const float4* b4 = (const float4*)b;
    out[i] = b4[i & 31];   // 128 cols = 32 float4, row-major
}

// xw = x @ W. 32 rows/block, 256 threads, each thread computes 4 rows x 4 cols.
__global__ __launch_bounds__(256)
void gemm_xw_kernel(const float* __restrict__ x, const float* __restrict__ W, int n) {
    __shared__ float Ws[DOUT][DOUT];   // 64 KB
    __shared__ float xs[32][DOUT];     // 16 KB
    int tid = threadIdx.x;

    // Load W (16384 floats = 4096 float4, 16 per thread)
    const float4* W4 = (const float4*)W;
    float4* Ws4 = (float4*)Ws;
    #pragma unroll
    for (int i = 0; i < 16; i++) Ws4[tid + i * 256] = W4[tid + i * 256];

    // Load x tile (32x128 = 1024 float4, 4 per thread)
    int row0 = blockIdx.x * 32;
    const float4* x4 = (const float4*)(x + (size_t)row0 * DOUT);
    float4* xs4 = (float4*)xs;
    #pragma unroll
    for (int i = 0; i < 4; i++) {
        int idx = tid + i * 256;
        int grow = row0 + (idx >> 5);
        if (grow < n) xs4[idx] = x4[idx];
    }
    __syncthreads();

    int rg = tid >> 5;    // warp id -> row group (rows rg*4 .. rg*4+3)
    int cg = tid & 31;    // lane -> col group (cols cg*4 .. cg*4+3)

    float4 acc0 = {0,0,0,0}, acc1 = {0,0,0,0}, acc2 = {0,0,0,0}, acc3 = {0,0,0,0};
    #pragma unroll 8
    for (int k = 0; k < DOUT; k++) {
        float4 w = *(const float4*)&Ws[k][cg * 4];  // conflict-free: 32 lanes x 16B
        float x0 = xs[rg * 4 + 0][k];               // broadcast within warp
        float x1 = xs[rg * 4 + 1][k];
        float x2 = xs[rg * 4 + 2][k];
        float x3 = xs[rg * 4 + 3][k];
        acc0.x += x0 * w.x; acc0.y += x0 * w.y; acc0.z += x0 * w.z; acc0.w += x0 * w.w;
        acc1.x += x1 * w.x; acc1.y += x1 * w.y; acc1.z += x1 * w.z; acc1.w += x1 * w.w;
        acc2.x += x2 * w.x; acc2.y += x2 * w.y; acc2.z += x2 * w.z; acc2.w += x2 * w.w;
        acc3.x += x3 * w.x; acc3.y += x3 * w.y; acc3.z += x3 * w.z; acc3.w += x3 * w.w;
    }

    float4 accs[4] = {acc0, acc1, acc2, acc3};
    #pragma unroll
    for (int r = 0; r < 4; r++) {
        int grow = row0 + rg * 4 + r;
        if (grow < n)
            *(float4*)&g_xw[(size_t)grow * DOUT + cg * 4] = accs[r];
    }
}

// One warp per edge (grid-stride). Per edge:
//  ew_row = edge_attr[e] @ edge_w  (16-step shfl dot, edge_w in smem)
//  msg    = xw[src] * ew_row       (float4 gather, L2-resident)
//  red.global.add.v4.f32 to out[dst]
__global__ __launch_bounds__(256)
void edge_kernel(const int* __restrict__ ei,
                 const float* __restrict__ ea,
                 const float* __restrict__ ew,
                 float* __restrict__ out, int nE) {
    __shared__ float ews[EDIM][DOUT];  // 8 KB
    int tid = threadIdx.x;

    const float4* ew4 = (const float4*)ew;
    float4* ews4 = (float4*)ews;
    #pragma unroll
    for (int i = 0; i < 2; i++) ews4[tid + i * 256] = ew4[tid + i * 256];
    __syncthreads();

    int lane = tid & 31;
    int gwarp = blockIdx.x * 8 + (tid >> 5);
    int nwarps = gridDim.x * 8;

    for (int e = gwarp; e < nE; e += nwarps) {
        float a = (lane < EDIM) ? ea[(size_t)e * EDIM + lane] : 0.0f;
        int src = ei[e];
        int dst = ei[nE + e];

        float4 ac = {0,0,0,0};
        #pragma unroll
        for (int k = 0; k < EDIM; k++) {
            float ak = __shfl_sync(0xffffffffu, a, k);
            float4 w = *(const float4*)&ews[k][lane * 4];
            ac.x += ak * w.x; ac.y += ak * w.y; ac.z += ak * w.z; ac.w += ak * w.w;
        }

        float4 xv = *(const float4*)&g_xw[(size_t)src * DOUT + lane * 4];
        float4 m;
        m.x = ac.x * xv.x; m.y = ac.y * xv.y; m.z = ac.z * xv.z; m.w = ac.w * xv.w;

        float* dp = &out[(size_t)dst * DOUT + lane * 4];
        asm volatile("red.global.add.v4.f32 [%0], {%1, %2, %3, %4};"
                     :: "l"(dp), "f"(m.x), "f"(m.y), "f"(m.z), "f"(m.w)
                     : "memory");
    }
}

extern "C" void kernel_launch(void* const* d_in, const int* in_sizes, int n_in,
                              void* d_out, int out_size) {
    const float* x  = (const float*)d_in[0];
    const int*   ei = (const int*)d_in[1];
    const float* ea = (const float*)d_in[2];
    const float* W  = (const float*)d_in[3];
    const float* ew = (const float*)d_in[4];
    const float* b  = (const float*)d_in[5];
    float* out = (float*)d_out;

    int n  = in_sizes[0] / DOUT;   // 100000 nodes
    int nE = in_sizes[1] / 2;      // 800000 edges (edge_index is [2, E] int32)

    int n4 = (n * DOUT) / 4;
    init_out_kernel<<<(n4 + 255) / 256, 256>>>(b, (float4*)out, n4);
    gemm_xw_kernel<<<(n + 31) / 32, 256>>>(x, W, n);
    edge_kernel<<<4096, 256>>>(ei, ea, ew, out, nE);
}